// round 5
// baseline (speedup 1.0000x reference)
#include <cuda_runtime.h>
#include <cuda_bf16.h>
#include <cstdint>
#include <cstddef>

#define NN 100000
#define EE 800000

// ---------------- scratch (static __device__ globals; no allocation) ----------------
__device__ float d_P[NN * 64];
__device__ float d_AGG[NN * 64];
__device__ float d_CB[NN * 96];
__device__ float d_T1[NN * 96];
__device__ float d_T2[NN * 96];
__device__ int   d_dgo[NN];
__device__ int   d_dgi[NN];
__device__ float d_stats[1152];
__device__ float d_c1f[64], d_c2f[64], d_c3f[64];
__device__ float d_d1f[96], d_d2f[96], d_d3f[32];
// pre-split transposed weight blobs: [Wh: NC*(K+8) bf16][Wl: NC*(K+8) bf16]
__device__ uint4 d_Bp[640];     // W1 rows 0..31  -> K=32, NC=64, KP=40
__device__ uint4 d_Be1[640];    // W1 rows 32..63 -> K=32, NC=64, KP=40
__device__ uint4 d_Be2[1152];   // W2  K=64, NC=64, KP=72
__device__ uint4 d_Bl3[1152];   // W3  K=64, NC=64, KP=72
__device__ uint4 d_Bm1[2496];   // V1  K=96, NC=96, KP=104
__device__ uint4 d_Bm2[2496];   // V2  K=96, NC=96, KP=104
__device__ uint4 d_Bo[832];     // V3  K=96, NC=32, KP=104

__device__ __forceinline__ float lrelu(float v) { return v > 0.f ? v : 0.1f * v; }

__device__ __forceinline__ void red_add_v4(float* p, float4 v) {
    asm volatile("red.global.add.v4.f32 [%0], {%1,%2,%3,%4};"
                 :: "l"(p), "f"(v.x), "f"(v.y), "f"(v.z), "f"(v.w) : "memory");
}

__device__ __forceinline__ uint32_t pack_hi(float a0, float a1, uint32_t& lo) {
    __nv_bfloat16 h0 = __float2bfloat16(a0), h1 = __float2bfloat16(a1);
    __nv_bfloat16 l0 = __float2bfloat16(a0 - __bfloat162float(h0));
    __nv_bfloat16 l1 = __float2bfloat16(a1 - __bfloat162float(h1));
    lo = (uint32_t)__bfloat16_as_ushort(l0) | ((uint32_t)__bfloat16_as_ushort(l1) << 16);
    return (uint32_t)__bfloat16_as_ushort(h0) | ((uint32_t)__bfloat16_as_ushort(h1) << 16);
}

// ---------------- shared mma core: 128 rows x NC, 3-term bf16 split ----------------
template <int K, int NC>
__device__ __forceinline__ void mma_block(
    const __nv_bfloat16* __restrict__ Ah, const __nv_bfloat16* __restrict__ Al,
    const __nv_bfloat16* __restrict__ Wh, const __nv_bfloat16* __restrict__ Wl,
    float (&acc)[2][NC / 8][4], int wrp, int g8, int tg) {
    constexpr int KP = K + 8, NT = NC / 8, KS = K / 16;
    const __nv_bfloat16* APTR[3] = {Ah, Ah, Al};
    const __nv_bfloat16* WPTR[3] = {Wh, Wl, Wh};
#pragma unroll
    for (int t = 0; t < 3; t++) {
        const __nv_bfloat16* Ab = APTR[t];
        const __nv_bfloat16* Wb = WPTR[t];
#pragma unroll
        for (int ks = 0; ks < KS; ks++) {
            uint32_t a[2][4];
#pragma unroll
            for (int mt = 0; mt < 2; mt++) {
                int row = wrp * 32 + mt * 16 + g8;
                const uint32_t* p  = (const uint32_t*)(Ab + row * KP + ks * 16 + tg * 2);
                const uint32_t* p8 = (const uint32_t*)(Ab + (row + 8) * KP + ks * 16 + tg * 2);
                a[mt][0] = p[0];  a[mt][1] = p8[0];
                a[mt][2] = p[4];  a[mt][3] = p8[4];
            }
#pragma unroll
            for (int nt = 0; nt < NT; nt++) {
                const uint32_t* q = (const uint32_t*)(Wb + (nt * 8 + g8) * KP + ks * 16 + tg * 2);
                uint32_t b0 = q[0], b1 = q[4];
#pragma unroll
                for (int mt = 0; mt < 2; mt++) {
                    asm volatile(
                        "mma.sync.aligned.m16n8k16.row.col.f32.bf16.bf16.f32 "
                        "{%0,%1,%2,%3}, {%4,%5,%6,%7}, {%8,%9}, {%0,%1,%2,%3};"
                        : "+f"(acc[mt][nt][0]), "+f"(acc[mt][nt][1]),
                          "+f"(acc[mt][nt][2]), "+f"(acc[mt][nt][3])
                        : "r"(a[mt][0]), "r"(a[mt][1]), "r"(a[mt][2]), "r"(a[mt][3]),
                          "r"(b0), "r"(b1));
                }
            }
        }
    }
}

// ---------------- zero scratch ----------------
__global__ void zero_k(float* agg, int* dgo, int* dgi, float* st) {
    int i = blockIdx.x * blockDim.x + threadIdx.x;
    int stride = gridDim.x * blockDim.x;
    for (int j = i; j < NN * 64; j += stride) agg[j] = 0.f;
    for (int j = i; j < NN; j += stride) { dgo[j] = 0; dgi[j] = 0; }
    for (int j = i; j < 1152; j += stride) st[j] = 0.f;
}

// ---------------- degree counts ----------------
__global__ void deg_k(const int* __restrict__ ei, int* dgo, int* dgi) {
    int i = blockIdx.x * blockDim.x + threadIdx.x;
    int stride = gridDim.x * blockDim.x;
    for (int e = i; e < EE; e += stride) {
        atomicAdd(&dgo[ei[e]], 1);
        atomicAdd(&dgi[ei[EE + e]], 1);
    }
}

// ---------------- 32-wide column stats ----------------
template <int MODE>
__global__ void colstats_k(const float* __restrict__ A, int nrows,
                           const int* __restrict__ w, float* __restrict__ cb,
                           float* __restrict__ sum, float* __restrict__ sq) {
    int tid = threadIdx.x;
    int c = tid & 31;
    int i = blockIdx.x * blockDim.x + tid;
    int stride = gridDim.x * blockDim.x;
    float s = 0.f, q = 0.f;
    int tot = nrows * 32;
    for (int j = i; j < tot; j += stride) {
        float v = A[j];
        if (MODE == 1) {
            float wf = (float)w[j >> 5];
            s += wf * v; q += wf * v * v;
        } else {
            s += v; q += v * v;
            if (MODE == 2) cb[(j >> 5) * 96 + (j & 31)] = v;
        }
    }
    __shared__ float red[256];
    red[tid] = s;
    __syncthreads();
    if (tid < 32) {
        float a = 0.f;
#pragma unroll
        for (int g = 0; g < 8; g++) a += red[tid + 32 * g];
        atomicAdd(&sum[c], a);
    }
    __syncthreads();
    red[tid] = q;
    __syncthreads();
    if (tid < 32) {
        float a = 0.f;
#pragma unroll
        for (int g = 0; g < 8; g++) a += red[tid + 32 * g];
        atomicAdd(&sq[c], a);
    }
}

// ---------------- fold BN into next Linear + emit split/transposed blob ----------------
// s = g*rsqrt(var+eps); t = b - mean*s;  Wf = diag(s)W (-> blob), cf = t@W + c
// rows k<ksplit go to blobA (KPa=ksplit+8, local k), rows k>=ksplit to blobB.
__global__ void foldprep_k(int K, int NC, int ksplit,
                           const float* __restrict__ g, const float* __restrict__ b,
                           const float* __restrict__ W, const float* __restrict__ c,
                           const float* __restrict__ ssum, const float* __restrict__ ssq,
                           float inv_cnt,
                           __nv_bfloat16* __restrict__ blobA,
                           __nv_bfloat16* __restrict__ blobB,
                           float* __restrict__ cf) {
    __shared__ float s[96], t[96];
    int tid = threadIdx.x;
    if (tid < K) {
        float m = ssum[tid] * inv_cnt;
        float v = ssq[tid] * inv_cnt - m * m;
        float sc = g[tid] * rsqrtf(v + 1e-5f);
        s[tid] = sc;
        t[tid] = b[tid] - m * sc;
    }
    __syncthreads();
    int KPa = ksplit + 8, KPb = (K - ksplit) + 8;
    for (int j = tid; j < NC; j += blockDim.x) {
        float acc = c[j];
        for (int k = 0; k < K; k++) acc += t[k] * W[k * NC + j];
        cf[j] = acc;
    }
    for (int i = tid; i < K * NC; i += blockDim.x) {
        int k = i / NC, n = i - k * NC;
        float w = s[k] * W[i];
        __nv_bfloat16 h = __float2bfloat16(w);
        __nv_bfloat16 l = __float2bfloat16(w - __bfloat162float(h));
        if (k < ksplit) {
            blobA[n * KPa + k] = h;
            blobA[NC * KPa + n * KPa + k] = l;
        } else {
            int kk = k - ksplit;
            blobB[n * KPb + kk] = h;
            blobB[NC * KPb + n * KPb + kk] = l;
        }
    }
}

// ---------------- node-side fused GEMM (mma.sync) ----------------
template <int K, int NC, bool RELU, bool STATS, bool DEGBIAS>
__global__ void __launch_bounds__(128)
tgemm_k(const float* __restrict__ A, int lda, int M,
        const uint4* __restrict__ Bblob, const float* __restrict__ bias,
        float* __restrict__ out, int ldo, int ocol,
        const int* __restrict__ degb,
        float* __restrict__ ssum, float* __restrict__ ssq) {
    constexpr int KP = K + 8;
    constexpr int SW = NC + 2;
    constexpr int MAXW = (KP > SW) ? KP : SW;
    constexpr int S1 = 128 * MAXW * 4;
    constexpr int NT = NC / 8;

    extern __shared__ unsigned char sm[];
    __nv_bfloat16* smAh = (__nv_bfloat16*)sm;
    __nv_bfloat16* smAl = smAh + 128 * KP;
    __nv_bfloat16* smWh = (__nv_bfloat16*)(sm + S1);
    float* stg = (float*)sm;

    const int tid = threadIdx.x;
    const int lane = tid & 31, wrp = tid >> 5;
    const int g8 = lane >> 2, tg = lane & 3;
    const int row0 = blockIdx.x * 128;

    {
        uint4* wd = (uint4*)smWh;
        for (int i = tid; i < NC * KP / 4; i += 128) wd[i] = Bblob[i];
    }
    {
        constexpr int KH = K / 2;
        for (int idx = tid; idx < 128 * KH; idx += 128) {
            int row = idx / KH;
            int k = (idx - row * KH) * 2;
            int g = row0 + row;
            float ax = 0.f, ay = 0.f;
            if (g < M) {
                float2 t = *(const float2*)(A + (size_t)g * lda + k);
                ax = t.x; ay = t.y;
            }
            uint32_t lw, hw = pack_hi(ax, ay, lw);
            *(uint32_t*)(smAh + row * KP + k) = hw;
            *(uint32_t*)(smAl + row * KP + k) = lw;
        }
    }
    __syncthreads();

    float acc[2][NT][4];
#pragma unroll
    for (int mt = 0; mt < 2; mt++)
#pragma unroll
        for (int nt = 0; nt < NT; nt++)
#pragma unroll
            for (int j = 0; j < 4; j++) acc[mt][nt][j] = 0.f;

    mma_block<K, NC>(smAh, smAl, smWh, smWh + NC * KP, acc, wrp, g8, tg);
    __syncthreads();

#pragma unroll
    for (int mt = 0; mt < 2; mt++) {
        int r0 = wrp * 32 + mt * 16 + g8;
#pragma unroll
        for (int nt = 0; nt < NT; nt++) {
            int c = nt * 8 + tg * 2;
            *(float2*)&stg[r0 * SW + c]       = make_float2(acc[mt][nt][0], acc[mt][nt][1]);
            *(float2*)&stg[(r0 + 8) * SW + c] = make_float2(acc[mt][nt][2], acc[mt][nt][3]);
        }
    }
    __syncthreads();

    const int g = row0 + tid;
    const bool valid = g < M;
    float db = 1.f;
    if (DEGBIAS) db = valid ? (float)degb[g] : 0.f;

    float v[NC];
#pragma unroll
    for (int c = 0; c < NC; c += 2) {
        float2 t = *(float2*)&stg[tid * SW + c];
        v[c] = t.x; v[c + 1] = t.y;
    }
#pragma unroll
    for (int j = 0; j < NC; j++) {
        float b = bias ? __ldg(bias + j) : 0.f;
        float t = v[j] + db * b;
        if (RELU) t = lrelu(t);
        v[j] = t;
    }
    if (valid) {
#pragma unroll
        for (int j = 0; j < NC; j += 4)
            *(float4*)(out + (size_t)g * ldo + ocol + j) =
                make_float4(v[j], v[j + 1], v[j + 2], v[j + 3]);
    }
    if (STATS) {
#pragma unroll
        for (int c = 0; c < NC; c += 2)
            *(float2*)&stg[tid * SW + c] =
                make_float2(valid ? v[c] : 0.f, valid ? v[c + 1] : 0.f);
        __syncthreads();
        if (tid < NC) {
            float s = 0.f, q = 0.f;
            for (int r = 0; r < 128; r++) {
                float t = stg[r * SW + tid];
                s += t; q += t * t;
            }
            atomicAdd(&ssum[tid], s);
            atomicAdd(&ssq[tid], q);
        }
    }
}

// ---------------- fused edge pipeline ----------------
// H = lrelu(P[row] + ea@W1b + c1f)   (GEMM1, K=32 -> 64)
// STATSONLY: reduce column sum/sq of H (BN2 stats), done.
// else:      h2 = lrelu(H@W2f + c2f) (GEMM2, K=64 -> 64); BN3 stats;
//            scatter-add h2 into AGG[col] via red.global.add.v4.f32
template <bool STATSONLY>
__global__ void __launch_bounds__(128)
edge_k(const float* __restrict__ ea, const float* __restrict__ P,
       const int* __restrict__ rowi, const int* __restrict__ coli,
       const uint4* __restrict__ B1, const float* __restrict__ c1f,
       const uint4* __restrict__ B2, const float* __restrict__ c2f,
       float* __restrict__ AGG,
       float* __restrict__ ssum, float* __restrict__ ssq) {
    constexpr int KP1 = 40, KP2 = 72, SW = 68;
    extern __shared__ unsigned char sm[];
    __nv_bfloat16* eaH = (__nv_bfloat16*)sm;             // 128*40*2 = 10240
    __nv_bfloat16* eaL = eaH + 128 * KP1;                // +10240
    __nv_bfloat16* W1h = (__nv_bfloat16*)(sm + 20480);   // 64*40*2 = 5120
    __nv_bfloat16* W1l = W1h + 64 * KP1;                 // +5120 -> 30720
    float* stg = (float*)sm;                             // 128*68*4 = 34816 (overlays)
    __nv_bfloat16* Hh  = (__nv_bfloat16*)(sm + 34816);   // 128*72*2 = 18432
    __nv_bfloat16* Hl  = Hh + 128 * KP2;                 // -> 71680
    __nv_bfloat16* W2h = (__nv_bfloat16*)(sm + 71680);   // 64*72*2 = 9216
    __nv_bfloat16* W2l = W2h + 64 * KP2;                 // -> 90112

    const int tid = threadIdx.x;
    const int lane = tid & 31, wrp = tid >> 5;
    const int g8 = lane >> 2, tg = lane & 3;
    const int row0 = blockIdx.x * 128;

    {
        uint4* d = (uint4*)W1h;
        for (int i = tid; i < 640; i += 128) d[i] = B1[i];
    }
    if (!STATSONLY) {
        uint4* d = (uint4*)W2h;
        for (int i = tid; i < 1152; i += 128) d[i] = B2[i];
    }
    // ea split fill (EE % 128 == 0, no bounds check)
    for (int idx = tid; idx < 128 * 16; idx += 128) {
        int r = idx >> 4, k = (idx & 15) * 2;
        float2 t = *(const float2*)(ea + (size_t)(row0 + r) * 32 + k);
        uint32_t lw, hw = pack_hi(t.x, t.y, lw);
        *(uint32_t*)(eaH + r * KP1 + k) = hw;
        *(uint32_t*)(eaL + r * KP1 + k) = lw;
    }
    __syncthreads();

    // ---- GEMM1 ----
    float acc[2][8][4];
#pragma unroll
    for (int mt = 0; mt < 2; mt++)
#pragma unroll
        for (int nt = 0; nt < 8; nt++)
#pragma unroll
            for (int j = 0; j < 4; j++) acc[mt][nt][j] = 0.f;
    mma_block<32, 64>(eaH, eaL, W1h, W1l, acc, wrp, g8, tg);
    __syncthreads();

#pragma unroll
    for (int mt = 0; mt < 2; mt++) {
        int r0 = wrp * 32 + mt * 16 + g8;
#pragma unroll
        for (int nt = 0; nt < 8; nt++) {
            int c = nt * 8 + tg * 2;
            *(float2*)&stg[r0 * SW + c]       = make_float2(acc[mt][nt][0], acc[mt][nt][1]);
            *(float2*)&stg[(r0 + 8) * SW + c] = make_float2(acc[mt][nt][2], acc[mt][nt][3]);
        }
    }
    __syncthreads();

    // ---- epilogue1: H = lrelu(stg + P[row] + c1f) ----
    {
        const int e = row0 + tid;
        const int src = rowi[e];
        float v[64];
#pragma unroll
        for (int c = 0; c < 64; c += 2) {
            float2 t = *(float2*)&stg[tid * SW + c];
            v[c] = t.x; v[c + 1] = t.y;
        }
#pragma unroll
        for (int j = 0; j < 64; j += 4) {
            float4 p = *(const float4*)(P + (size_t)src * 64 + j);
            v[j] += p.x; v[j + 1] += p.y; v[j + 2] += p.z; v[j + 3] += p.w;
        }
#pragma unroll
        for (int j = 0; j < 64; j++) v[j] = lrelu(v[j] + __ldg(c1f + j));

        if (STATSONLY) {
            __syncthreads();
#pragma unroll
            for (int c = 0; c < 64; c += 2)
                *(float2*)&stg[tid * SW + c] = make_float2(v[c], v[c + 1]);
            __syncthreads();
            if (tid < 64) {
                float s = 0.f, q = 0.f;
                for (int r = 0; r < 128; r++) {
                    float t = stg[r * SW + tid];
                    s += t; q += t * t;
                }
                atomicAdd(&ssum[tid], s);
                atomicAdd(&ssq[tid], q);
            }
            return;
        }
        // split H into smem (hi/lo) for GEMM2
#pragma unroll
        for (int k = 0; k < 64; k += 2) {
            uint32_t lw, hw = pack_hi(v[k], v[k + 1], lw);
            *(uint32_t*)(Hh + tid * KP2 + k) = hw;
            *(uint32_t*)(Hl + tid * KP2 + k) = lw;
        }
    }
    __syncthreads();

    // ---- GEMM2 ----
    float acc2[2][8][4];
#pragma unroll
    for (int mt = 0; mt < 2; mt++)
#pragma unroll
        for (int nt = 0; nt < 8; nt++)
#pragma unroll
            for (int j = 0; j < 4; j++) acc2[mt][nt][j] = 0.f;
    mma_block<64, 64>(Hh, Hl, W2h, W2l, acc2, wrp, g8, tg);
    __syncthreads();

#pragma unroll
    for (int mt = 0; mt < 2; mt++) {
        int r0 = wrp * 32 + mt * 16 + g8;
#pragma unroll
        for (int nt = 0; nt < 8; nt++) {
            int c = nt * 8 + tg * 2;
            *(float2*)&stg[r0 * SW + c]       = make_float2(acc2[mt][nt][0], acc2[mt][nt][1]);
            *(float2*)&stg[(r0 + 8) * SW + c] = make_float2(acc2[mt][nt][2], acc2[mt][nt][3]);
        }
    }
    __syncthreads();

    // ---- epilogue2: h2 = lrelu(stg + c2f); write back for scatter+stats ----
    {
        float v[64];
#pragma unroll
        for (int c = 0; c < 64; c += 2) {
            float2 t = *(float2*)&stg[tid * SW + c];
            v[c] = t.x; v[c + 1] = t.y;
        }
#pragma unroll
        for (int j = 0; j < 64; j++) v[j] = lrelu(v[j] + __ldg(c2f + j));
        __syncthreads();
#pragma unroll
        for (int c = 0; c < 64; c += 2)
            *(float2*)&stg[tid * SW + c] = make_float2(v[c], v[c + 1]);
    }
    __syncthreads();

    // ---- scatter: 2 rows per warp pass, 16B vector reductions ----
    for (int rr = wrp * 2; rr < 128; rr += 8) {
        int r = rr + (lane >> 4);
        int ch = (lane & 15) * 4;
        int dst = coli[row0 + r];
        float4 t = *(float4*)&stg[r * SW + ch];
        red_add_v4(AGG + (size_t)dst * 64 + ch, t);
    }

    // ---- BN3 column stats ----
    if (tid < 64) {
        float s = 0.f, q = 0.f;
        for (int r = 0; r < 128; r++) {
            float t = stg[r * SW + tid];
            s += t; q += t * t;
        }
        atomicAdd(&ssum[tid], s);
        atomicAdd(&ssq[tid], q);
    }
}

// ---------------- host ----------------
#define SYM(ptr, arr) do { void* _p = nullptr; cudaGetSymbolAddress(&_p, arr); ptr = (decltype(ptr))_p; } while (0)

static constexpr int smem_sz(int K, int NC) {
    int KP = K + 8, SW = NC + 2;
    int MAXW = KP > SW ? KP : SW;
    return 128 * MAXW * 4 + NC * KP * 4;
}

extern "C" void kernel_launch(void* const* d_in, const int* in_sizes, int n_in,
                              void* d_out, int out_size) {
    const float* x  = (const float*)d_in[0];
    const int*   ei = (const int*)d_in[1];
    const float* ea = (const float*)d_in[2];
    const float* m1_g1 = (const float*)d_in[5],  *m1_b1 = (const float*)d_in[6];
    const float* m1_w1 = (const float*)d_in[7],  *m1_c1 = (const float*)d_in[8];
    const float* m1_g2 = (const float*)d_in[9],  *m1_b2 = (const float*)d_in[10];
    const float* m1_w2 = (const float*)d_in[11], *m1_c2 = (const float*)d_in[12];
    const float* m1_g3 = (const float*)d_in[13], *m1_b3 = (const float*)d_in[14];
    const float* m1_w3 = (const float*)d_in[15], *m1_c3 = (const float*)d_in[16];
    const float* m2_g1 = (const float*)d_in[17], *m2_b1 = (const float*)d_in[18];
    const float* m2_w1 = (const float*)d_in[19], *m2_c1 = (const float*)d_in[20];
    const float* m2_g2 = (const float*)d_in[21], *m2_b2 = (const float*)d_in[22];
    const float* m2_w2 = (const float*)d_in[23], *m2_c2 = (const float*)d_in[24];
    const float* m2_g3 = (const float*)d_in[25], *m2_b3 = (const float*)d_in[26];
    const float* m2_w3 = (const float*)d_in[27], *m2_c3 = (const float*)d_in[28];

    float *P, *AGG, *CB, *T1, *T2, *ST;
    int *dgo, *dgi;
    float *c1f, *c2f, *c3f, *d1f, *d2f, *d3f;
    uint4 *Bp, *Be1, *Be2, *Bl3, *Bm1, *Bm2, *Bo;
    SYM(P, d_P); SYM(AGG, d_AGG); SYM(CB, d_CB);
    SYM(T1, d_T1); SYM(T2, d_T2); SYM(ST, d_stats);
    SYM(dgo, d_dgo); SYM(dgi, d_dgi);
    SYM(c1f, d_c1f); SYM(c2f, d_c2f); SYM(c3f, d_c3f);
    SYM(d1f, d_d1f); SYM(d2f, d_d2f); SYM(d3f, d_d3f);
    SYM(Bp, d_Bp); SYM(Be1, d_Be1); SYM(Be2, d_Be2); SYM(Bl3, d_Bl3);
    SYM(Bm1, d_Bm1); SYM(Bm2, d_Bm2); SYM(Bo, d_Bo);

    float *S0S = ST + 0,   *S0Q = ST + 96;
    float *S2S = ST + 192, *S2Q = ST + 288;
    float *S3S = ST + 384, *S3Q = ST + 480;
    float *B1S = ST + 576, *B1Q = ST + 672;
    float *B2S = ST + 768, *B2Q = ST + 864;
    float *B3S = ST + 960, *B3Q = ST + 1056;

    auto kP  = tgemm_k<32, 64, false, false, false>;
    auto kL3 = tgemm_k<64, 64, false, true,  true >;
    auto kM2 = tgemm_k<96, 96, true,  true,  false>;
    auto kO  = tgemm_k<96, 32, false, false, false>;
    auto kES = edge_k<true>;
    auto kEF = edge_k<false>;

    constexpr int smP   = smem_sz(32, 64);   // 44032
    constexpr int smL3  = smem_sz(64, 64);   // 55296
    constexpr int smM2  = smem_sz(96, 96);   // 93184
    constexpr int smO   = smem_sz(96, 32);   // 66560
    constexpr int smES  = 34816;
    constexpr int smEF  = 90112;

    cudaFuncSetAttribute(kP,  cudaFuncAttributeMaxDynamicSharedMemorySize, smP);
    cudaFuncSetAttribute(kL3, cudaFuncAttributeMaxDynamicSharedMemorySize, smL3);
    cudaFuncSetAttribute(kM2, cudaFuncAttributeMaxDynamicSharedMemorySize, smM2);
    cudaFuncSetAttribute(kO,  cudaFuncAttributeMaxDynamicSharedMemorySize, smO);
    cudaFuncSetAttribute(kES, cudaFuncAttributeMaxDynamicSharedMemorySize, smES);
    cudaFuncSetAttribute(kEF, cudaFuncAttributeMaxDynamicSharedMemorySize, smEF);

    const float invE = 1.f / (float)EE;
    const float invN = 1.f / (float)NN;
    const int EB = EE / 128;             // 6250
    const int NB = (NN + 127) / 128;     // 782

    zero_k<<<2048, 256>>>(AGG, dgo, dgi, ST);
    deg_k<<<512, 256>>>(ei, dgo, dgi);

    colstats_k<0><<<512, 256>>>(ea, EE, nullptr, nullptr, S0S + 32, S0Q + 32);
    colstats_k<1><<<256, 256>>>(x, NN, dgo, nullptr, S0S, S0Q);
    colstats_k<2><<<256, 256>>>(x, NN, nullptr, CB, B1S, B1Q);

    // fold BN1 -> blobs Bp (x-half, K=32) + Be1 (ea-half, K=32), bias c1f
    foldprep_k<<<1, 128>>>(64, 64, 32, m1_g1, m1_b1, m1_w1, m1_c1, S0S, S0Q, invE,
                           (__nv_bfloat16*)Bp, (__nv_bfloat16*)Be1, c1f);

    // P = x @ W1f[0:32]
    kP<<<NB, 128, smP>>>(x, 32, NN, Bp, nullptr, P, 64, 0, nullptr, nullptr, nullptr);

    // BN2 stats pass (recompute H, no store)
    kES<<<EB, 128, smES>>>(ea, P, ei, ei + EE, Be1, c1f, nullptr, nullptr,
                           nullptr, S2S, S2Q);

    foldprep_k<<<1, 128>>>(64, 64, 64, m1_g2, m1_b2, m1_w2, m1_c2, S2S, S2Q, invE,
                           (__nv_bfloat16*)Be2, nullptr, c2f);

    // fused: recompute H -> GEMM2 -> BN3 stats + scatter into AGG
    kEF<<<EB, 128, smEF>>>(ea, P, ei, ei + EE, Be1, c1f, Be2, c2f,
                           AGG, S3S, S3Q);

    foldprep_k<<<1, 128>>>(64, 64, 64, m1_g3, m1_b3, m1_w3, m1_c3, S3S, S3Q, invE,
                           (__nv_bfloat16*)Bl3, nullptr, c3f);

    // CB[:,32:96] = AGG @ W3f + deg_in * c3f
    kL3<<<NB, 128, smL3>>>(AGG, 64, NN, Bl3, c3f, CB, 96, 32, dgi,
                           B1S + 32, B1Q + 32);

    foldprep_k<<<1, 128>>>(96, 96, 96, m2_g1, m2_b1, m2_w1, m2_c1, B1S, B1Q, invN,
                           (__nv_bfloat16*)Bm1, nullptr, d1f);

    kM2<<<NB, 128, smM2>>>(CB, 96, NN, Bm1, d1f, T1, 96, 0, nullptr, B2S, B2Q);

    foldprep_k<<<1, 128>>>(96, 96, 96, m2_g2, m2_b2, m2_w2, m2_c2, B2S, B2Q, invN,
                           (__nv_bfloat16*)Bm2, nullptr, d2f);

    kM2<<<NB, 128, smM2>>>(T1, 96, NN, Bm2, d2f, T2, 96, 0, nullptr, B3S, B3Q);

    foldprep_k<<<1, 128>>>(96, 32, 96, m2_g3, m2_b3, m2_w3, m2_c3, B3S, B3Q, invN,
                           (__nv_bfloat16*)Bo, nullptr, d3f);

    kO<<<NB, 128, smO>>>(T2, 96, NN, Bo, d3f, (float*)d_out, 32, 0, nullptr,
                         nullptr, nullptr);
}

// round 6
// speedup vs baseline: 1.1044x; 1.1044x over previous
#include <cuda_runtime.h>
#include <cuda_bf16.h>
#include <cstdint>
#include <cstddef>

#define NN 100000
#define EE 800000

// ---------------- scratch (static __device__ globals; no allocation) ----------------
__device__ float d_P[NN * 64];
__device__ __nv_bfloat16 d_Hh[(size_t)EE * 64];
__device__ __nv_bfloat16 d_Hl[(size_t)EE * 64];
__device__ float d_AGG[NN * 64];
__device__ float d_CB[NN * 96];
__device__ float d_T1[NN * 96];
__device__ float d_T2[NN * 96];
__device__ int   d_dgo[NN];
__device__ int   d_dgi[NN];
__device__ float d_stats[1152];
__device__ float d_c1f[64], d_c2f[64], d_c3f[64];
__device__ float d_d1f[96], d_d2f[96], d_d3f[32];
// pre-split transposed weight blobs: [Wh: NC*(K+8) bf16][Wl: NC*(K+8) bf16]
__device__ uint4 d_Bp[640];     // W1 rows 0..31  -> K=32, NC=64, KP=40
__device__ uint4 d_Be1[640];    // W1 rows 32..63 -> K=32, NC=64, KP=40
__device__ uint4 d_Be2[1152];   // W2  K=64, NC=64, KP=72
__device__ uint4 d_Bl3[1152];   // W3  K=64, NC=64, KP=72
__device__ uint4 d_Bm1[2496];   // V1  K=96, NC=96, KP=104
__device__ uint4 d_Bm2[2496];   // V2  K=96, NC=96, KP=104
__device__ uint4 d_Bo[832];     // V3  K=96, NC=32, KP=104

__device__ __forceinline__ float lrelu(float v) { return v > 0.f ? v : 0.1f * v; }

__device__ __forceinline__ void red_add_v4(float* p, float4 v) {
    asm volatile("red.global.add.v4.f32 [%0], {%1,%2,%3,%4};"
                 :: "l"(p), "f"(v.x), "f"(v.y), "f"(v.z), "f"(v.w) : "memory");
}

__device__ __forceinline__ uint32_t pack_hi(float a0, float a1, uint32_t& lo) {
    __nv_bfloat16 h0 = __float2bfloat16(a0), h1 = __float2bfloat16(a1);
    __nv_bfloat16 l0 = __float2bfloat16(a0 - __bfloat162float(h0));
    __nv_bfloat16 l1 = __float2bfloat16(a1 - __bfloat162float(h1));
    lo = (uint32_t)__bfloat16_as_ushort(l0) | ((uint32_t)__bfloat16_as_ushort(l1) << 16);
    return (uint32_t)__bfloat16_as_ushort(h0) | ((uint32_t)__bfloat16_as_ushort(h1) << 16);
}

// ---------------- zero scratch ----------------
__global__ void zero_k(float* agg, int* dgo, int* dgi, float* st) {
    int i = blockIdx.x * blockDim.x + threadIdx.x;
    int stride = gridDim.x * blockDim.x;
    for (int j = i; j < NN * 64; j += stride) agg[j] = 0.f;
    for (int j = i; j < NN; j += stride) { dgo[j] = 0; dgi[j] = 0; }
    for (int j = i; j < 1152; j += stride) st[j] = 0.f;
}

// ---------------- degree counts ----------------
__global__ void deg_k(const int* __restrict__ ei, int* dgo, int* dgi) {
    int i = blockIdx.x * blockDim.x + threadIdx.x;
    int stride = gridDim.x * blockDim.x;
    for (int e = i; e < EE; e += stride) {
        atomicAdd(&dgo[ei[e]], 1);
        atomicAdd(&dgi[ei[EE + e]], 1);
    }
}

// ---------------- merged 32-wide column stats (3 segments) ----------------
// blocks [0,512):   plain stats of ea (EE x 32)        -> S0S+32 / S0Q+32
// blocks [512,768): degree-weighted stats of x         -> S0S / S0Q
// blocks [768,1024): stats of x + copy into CB[:,0:32] -> B1S / B1Q
__global__ void stats3_k(const float* __restrict__ ea, const float* __restrict__ x,
                         const int* __restrict__ dgo, float* __restrict__ cb,
                         float* __restrict__ ST) {
    int b = blockIdx.x, tid = threadIdx.x, c = tid & 31;
    const float* A; int nrows, lb, G, mode;
    float *sum, *sq;
    if (b < 512)      { mode = 0; A = ea; nrows = EE; lb = b;       G = 512; sum = ST + 32;        sq = ST + 96 + 32; }
    else if (b < 768) { mode = 1; A = x;  nrows = NN; lb = b - 512; G = 256; sum = ST;             sq = ST + 96; }
    else              { mode = 2; A = x;  nrows = NN; lb = b - 768; G = 256; sum = ST + 576;       sq = ST + 672; }
    int i = lb * 256 + tid, stride = G * 256, tot = nrows * 32;
    float s = 0.f, q = 0.f;
    for (int j = i; j < tot; j += stride) {
        float v = A[j];
        if (mode == 1) {
            float wf = (float)dgo[j >> 5];
            s += wf * v; q += wf * v * v;
        } else {
            s += v; q += v * v;
            if (mode == 2) cb[(j >> 5) * 96 + (j & 31)] = v;
        }
    }
    __shared__ float red[256];
    red[tid] = s;
    __syncthreads();
    if (tid < 32) {
        float a = 0.f;
#pragma unroll
        for (int g = 0; g < 8; g++) a += red[tid + 32 * g];
        atomicAdd(&sum[c], a);
    }
    __syncthreads();
    red[tid] = q;
    __syncthreads();
    if (tid < 32) {
        float a = 0.f;
#pragma unroll
        for (int g = 0; g < 8; g++) a += red[tid + 32 * g];
        atomicAdd(&sq[c], a);
    }
}

// ---------------- fold BN into next Linear + emit split/transposed blob ----------------
__global__ void foldprep_k(int K, int NC, int ksplit,
                           const float* __restrict__ g, const float* __restrict__ b,
                           const float* __restrict__ W, const float* __restrict__ c,
                           const float* __restrict__ ssum, const float* __restrict__ ssq,
                           float inv_cnt,
                           __nv_bfloat16* __restrict__ blobA,
                           __nv_bfloat16* __restrict__ blobB,
                           float* __restrict__ cf) {
    __shared__ float s[96], t[96];
    int tid = threadIdx.x;
    if (tid < K) {
        float m = ssum[tid] * inv_cnt;
        float v = ssq[tid] * inv_cnt - m * m;
        float sc = g[tid] * rsqrtf(v + 1e-5f);
        s[tid] = sc;
        t[tid] = b[tid] - m * sc;
    }
    __syncthreads();
    int KPa = ksplit + 8, KPb = (K - ksplit) + 8;
    for (int j = tid; j < NC; j += blockDim.x) {
        float acc = c[j];
        for (int k = 0; k < K; k++) acc += t[k] * W[k * NC + j];
        cf[j] = acc;
    }
    for (int i = tid; i < K * NC; i += blockDim.x) {
        int k = i / NC, n = i - k * NC;
        float w = s[k] * W[i];
        __nv_bfloat16 h = __float2bfloat16(w);
        __nv_bfloat16 l = __float2bfloat16(w - __bfloat162float(h));
        if (k < ksplit) {
            blobA[n * KPa + k] = h;
            blobA[NC * KPa + n * KPa + k] = l;
        } else {
            int kk = k - ksplit;
            blobB[n * KPb + kk] = h;
            blobB[NC * KPb + n * KPb + kk] = l;
        }
    }
}

// ---------------- mma.sync fused GEMM: out[M,NC] = epi(A[M,K] @ W[K,NC]) ----------------
// bf16 3-term split: D = Ah*Wh + Ah*Wl + Al*Wh. 128 rows/block, 4 warps.
template <int K, int NC, bool RELU, bool STATS, bool GATHERP, bool SCATTER,
          bool DEGBIAS, bool ASPLIT, bool OUTSPLIT>
__global__ void __launch_bounds__(128)
tgemm_k(const float* __restrict__ A, int lda, int M,
        const __nv_bfloat16* __restrict__ Ahg, const __nv_bfloat16* __restrict__ Alg,
        const uint4* __restrict__ Bblob,
        const float* __restrict__ bias,
        float* __restrict__ out, int ldo, int ocol,
        __nv_bfloat16* __restrict__ Oh, __nv_bfloat16* __restrict__ Ol,
        const float* __restrict__ Pg, const int* __restrict__ gidx,
        const int* __restrict__ degb,
        float* __restrict__ ssum, float* __restrict__ ssq) {
    constexpr int KP = K + 8;                    // padded row -> conflict-free frags
    constexpr int SW = NC + 2;                   // staging row stride (floats)
    constexpr int MAXW = (KP > SW) ? KP : SW;
    constexpr int S1 = 128 * MAXW * 4;           // bytes: A(hi+lo) region, reused as staging
    constexpr int NT = NC / 8;
    constexpr int KS = K / 16;

    extern __shared__ unsigned char sm[];
    __nv_bfloat16* smAh = (__nv_bfloat16*)sm;
    __nv_bfloat16* smAl = smAh + 128 * KP;
    __nv_bfloat16* smWh = (__nv_bfloat16*)(sm + S1);
    __nv_bfloat16* smWl = smWh + NC * KP;
    float* stg = (float*)sm;

    const int tid = threadIdx.x;
    const int lane = tid & 31, wrp = tid >> 5;
    const int g8 = lane >> 2, tg = lane & 3;
    const int row0 = blockIdx.x * 128;

    // ---- W copy (blob layout == smem layout) ----
    {
        uint4* wd = (uint4*)smWh;
        for (int i = tid; i < NC * KP / 4; i += 128) wd[i] = Bblob[i];
    }
    // ---- A fill (+ fp32->bf16 hi/lo split unless pre-split) ----
    {
        constexpr int KH = K / 2;
        for (int idx = tid; idx < 128 * KH; idx += 128) {
            int row = idx / KH;
            int k = (idx - row * KH) * 2;
            int g = row0 + row;
            uint32_t hw = 0, lw = 0;
            if (ASPLIT) {
                if (g < M) {
                    hw = *(const uint32_t*)(Ahg + (size_t)g * K + k);
                    lw = *(const uint32_t*)(Alg + (size_t)g * K + k);
                }
            } else {
                float ax = 0.f, ay = 0.f;
                if (g < M) {
                    float2 t = *(const float2*)(A + (size_t)g * lda + k);
                    ax = t.x; ay = t.y;
                }
                hw = pack_hi(ax, ay, lw);
            }
            *(uint32_t*)(smAh + row * KP + k) = hw;
            *(uint32_t*)(smAl + row * KP + k) = lw;
        }
    }
    __syncthreads();

    // ---- mma compute ----
    float acc[2][NT][4];
#pragma unroll
    for (int mt = 0; mt < 2; mt++)
#pragma unroll
        for (int nt = 0; nt < NT; nt++)
#pragma unroll
            for (int j = 0; j < 4; j++) acc[mt][nt][j] = 0.f;

    const __nv_bfloat16* APTR[3] = {smAh, smAh, smAl};
    const __nv_bfloat16* WPTR[3] = {smWh, smWl, smWh};
#pragma unroll
    for (int t = 0; t < 3; t++) {
        const __nv_bfloat16* Ab = APTR[t];
        const __nv_bfloat16* Wb = WPTR[t];
#pragma unroll
        for (int ks = 0; ks < KS; ks++) {
            uint32_t a[2][4];
#pragma unroll
            for (int mt = 0; mt < 2; mt++) {
                int row = wrp * 32 + mt * 16 + g8;
                const uint32_t* p  = (const uint32_t*)(Ab + row * KP + ks * 16 + tg * 2);
                const uint32_t* p8 = (const uint32_t*)(Ab + (row + 8) * KP + ks * 16 + tg * 2);
                a[mt][0] = p[0];  a[mt][1] = p8[0];
                a[mt][2] = p[4];  a[mt][3] = p8[4];
            }
#pragma unroll
            for (int nt = 0; nt < NT; nt++) {
                const uint32_t* q = (const uint32_t*)(Wb + (nt * 8 + g8) * KP + ks * 16 + tg * 2);
                uint32_t b0 = q[0], b1 = q[4];
#pragma unroll
                for (int mt = 0; mt < 2; mt++) {
                    asm volatile(
                        "mma.sync.aligned.m16n8k16.row.col.f32.bf16.bf16.f32 "
                        "{%0,%1,%2,%3}, {%4,%5,%6,%7}, {%8,%9}, {%0,%1,%2,%3};"
                        : "+f"(acc[mt][nt][0]), "+f"(acc[mt][nt][1]),
                          "+f"(acc[mt][nt][2]), "+f"(acc[mt][nt][3])
                        : "r"(a[mt][0]), "r"(a[mt][1]), "r"(a[mt][2]), "r"(a[mt][3]),
                          "r"(b0), "r"(b1));
                }
            }
        }
    }
    __syncthreads();   // A reads done; staging may overwrite

    // ---- fragments -> staging ----
#pragma unroll
    for (int mt = 0; mt < 2; mt++) {
        int r0 = wrp * 32 + mt * 16 + g8;
#pragma unroll
        for (int nt = 0; nt < NT; nt++) {
            int c = nt * 8 + tg * 2;
            *(float2*)&stg[r0 * SW + c]       = make_float2(acc[mt][nt][0], acc[mt][nt][1]);
            *(float2*)&stg[(r0 + 8) * SW + c] = make_float2(acc[mt][nt][2], acc[mt][nt][3]);
        }
    }
    __syncthreads();

    // ---- warp-cooperative P gather: 16 lanes x float4 per row, 2 rows/warp-pass ----
    if (GATHERP) {
        for (int rr = wrp * 2; rr < 128; rr += 8) {
            int r = rr + (lane >> 4);
            int ch = (lane & 15) * 4;
            int e = row0 + r;
            if (e < M) {
                int src = gidx[e];
                float4 p = *(const float4*)(Pg + (size_t)src * 64 + ch);
                float2 t0 = *(float2*)&stg[r * SW + ch];
                float2 t1 = *(float2*)&stg[r * SW + ch + 2];
                t0.x += p.x; t0.y += p.y; t1.x += p.z; t1.y += p.w;
                *(float2*)&stg[r * SW + ch] = t0;
                *(float2*)&stg[r * SW + ch + 2] = t1;
            }
        }
        __syncthreads();
    }

    // ---- per-row epilogue: thread tid owns row row0+tid ----
    const int g = row0 + tid;
    const bool valid = g < M;
    float db = 1.f;
    if (DEGBIAS) db = valid ? (float)degb[g] : 0.f;

#pragma unroll
    for (int ch = 0; ch < NC; ch += 32) {
        float v[32];
#pragma unroll
        for (int c = 0; c < 32; c += 2) {
            float2 t = *(float2*)&stg[tid * SW + ch + c];
            v[c] = t.x; v[c + 1] = t.y;
        }
#pragma unroll
        for (int j = 0; j < 32; j++) {
            float b = bias ? __ldg(bias + ch + j) : 0.f;
            float t = v[j] + db * b;
            if (RELU) t = lrelu(t);
            v[j] = t;
        }
        if (!SCATTER && !OUTSPLIT) {
            if (valid) {
#pragma unroll
                for (int j = 0; j < 32; j += 4)
                    *(float4*)(out + (size_t)g * ldo + ocol + ch + j) =
                        make_float4(v[j], v[j + 1], v[j + 2], v[j + 3]);
            }
        }
        if (STATS || SCATTER || OUTSPLIT) {
#pragma unroll
            for (int c = 0; c < 32; c += 2)
                *(float2*)&stg[tid * SW + ch + c] =
                    make_float2(valid ? v[c] : 0.f, valid ? v[c + 1] : 0.f);
        }
    }

    if (STATS || SCATTER || OUTSPLIT) __syncthreads();

    if (SCATTER) {
        // warp-cooperative 16B vector reductions (NC == 64)
        for (int rr = wrp * 2; rr < 128; rr += 8) {
            int r = rr + (lane >> 4);
            int gr = row0 + r;
            if (gr < M) {
                int ch = (lane & 15) * 4;
                int dst = gidx[gr];
                float2 t0 = *(float2*)&stg[r * SW + ch];
                float2 t1 = *(float2*)&stg[r * SW + ch + 2];
                red_add_v4(out + (size_t)dst * 64 + ch,
                           make_float4(t0.x, t0.y, t1.x, t1.y));
            }
        }
    }

    if (OUTSPLIT) {
        // coalesced packed split write (NC == 64)
        for (int i = tid; i < 128 * 32; i += 128) {
            int r = i >> 5, c2 = i & 31;
            int gr = row0 + r;
            if (gr < M) {
                uint32_t lw, hw = pack_hi(stg[r * SW + 2 * c2], stg[r * SW + 2 * c2 + 1], lw);
                ((uint32_t*)Oh)[(size_t)gr * 32 + c2] = hw;
                ((uint32_t*)Ol)[(size_t)gr * 32 + c2] = lw;
            }
        }
    }

    if (STATS) {
        if (tid < NC) {
            float s = 0.f, q = 0.f;
            for (int r = 0; r < 128; r++) {
                float t = stg[r * SW + tid];
                s += t; q += t * t;
            }
            atomicAdd(&ssum[tid], s);
            atomicAdd(&ssq[tid], q);
        }
    }
}

// ---------------- host ----------------
#define SYM(ptr, arr) do { void* _p = nullptr; cudaGetSymbolAddress(&_p, arr); ptr = (decltype(ptr))_p; } while (0)

static constexpr int smem_sz(int K, int NC) {
    int KP = K + 8, SW = NC + 2;
    int MAXW = KP > SW ? KP : SW;
    return 128 * MAXW * 4 + NC * KP * 4;
}

extern "C" void kernel_launch(void* const* d_in, const int* in_sizes, int n_in,
                              void* d_out, int out_size) {
    const float* x  = (const float*)d_in[0];
    const int*   ei = (const int*)d_in[1];
    const float* ea = (const float*)d_in[2];
    const float* m1_g1 = (const float*)d_in[5],  *m1_b1 = (const float*)d_in[6];
    const float* m1_w1 = (const float*)d_in[7],  *m1_c1 = (const float*)d_in[8];
    const float* m1_g2 = (const float*)d_in[9],  *m1_b2 = (const float*)d_in[10];
    const float* m1_w2 = (const float*)d_in[11], *m1_c2 = (const float*)d_in[12];
    const float* m1_g3 = (const float*)d_in[13], *m1_b3 = (const float*)d_in[14];
    const float* m1_w3 = (const float*)d_in[15], *m1_c3 = (const float*)d_in[16];
    const float* m2_g1 = (const float*)d_in[17], *m2_b1 = (const float*)d_in[18];
    const float* m2_w1 = (const float*)d_in[19], *m2_c1 = (const float*)d_in[20];
    const float* m2_g2 = (const float*)d_in[21], *m2_b2 = (const float*)d_in[22];
    const float* m2_w2 = (const float*)d_in[23], *m2_c2 = (const float*)d_in[24];
    const float* m2_g3 = (const float*)d_in[25], *m2_b3 = (const float*)d_in[26];
    const float* m2_w3 = (const float*)d_in[27], *m2_c3 = (const float*)d_in[28];

    float *P, *AGG, *CB, *T1, *T2, *ST;
    __nv_bfloat16 *Hh, *Hl;
    int *dgo, *dgi;
    float *c1f, *c2f, *c3f, *d1f, *d2f, *d3f;
    uint4 *Bp, *Be1, *Be2, *Bl3, *Bm1, *Bm2, *Bo;
    SYM(P, d_P); SYM(Hh, d_Hh); SYM(Hl, d_Hl); SYM(AGG, d_AGG); SYM(CB, d_CB);
    SYM(T1, d_T1); SYM(T2, d_T2); SYM(ST, d_stats);
    SYM(dgo, d_dgo); SYM(dgi, d_dgi);
    SYM(c1f, d_c1f); SYM(c2f, d_c2f); SYM(c3f, d_c3f);
    SYM(d1f, d_d1f); SYM(d2f, d_d2f); SYM(d3f, d_d3f);
    SYM(Bp, d_Bp); SYM(Be1, d_Be1); SYM(Be2, d_Be2); SYM(Bl3, d_Bl3);
    SYM(Bm1, d_Bm1); SYM(Bm2, d_Bm2); SYM(Bo, d_Bo);

    float *S0S = ST + 0,   *S0Q = ST + 96;
    float *S2S = ST + 192, *S2Q = ST + 288;
    float *S3S = ST + 384, *S3Q = ST + 480;
    float *B1S = ST + 576, *B1Q = ST + 672;
    float *B2S = ST + 768, *B2Q = ST + 864;
    float *B3S = ST + 960, *B3Q = ST + 1056;

    // <K,NC,RELU,STATS,GATHERP,SCATTER,DEGBIAS,ASPLIT,OUTSPLIT>
    auto kP  = tgemm_k<32, 64, false, false, false, false, false, false, false>;
    auto kE1 = tgemm_k<32, 64, true,  true,  true,  false, false, false, true >;
    auto kE2 = tgemm_k<64, 64, true,  true,  false, true,  false, true,  false>;
    auto kL3 = tgemm_k<64, 64, false, true,  false, false, true,  false, false>;
    auto kM2 = tgemm_k<96, 96, true,  true,  false, false, false, false, false>;
    auto kO  = tgemm_k<96, 32, false, false, false, false, false, false, false>;

    constexpr int smP  = smem_sz(32, 64);   // 44032
    constexpr int smE2 = smem_sz(64, 64);   // 55296
    constexpr int smM2 = smem_sz(96, 96);   // 93184
    constexpr int smO  = smem_sz(96, 32);   // 66560

    cudaFuncSetAttribute(kP,  cudaFuncAttributeMaxDynamicSharedMemorySize, smP);
    cudaFuncSetAttribute(kE1, cudaFuncAttributeMaxDynamicSharedMemorySize, smP);
    cudaFuncSetAttribute(kE2, cudaFuncAttributeMaxDynamicSharedMemorySize, smE2);
    cudaFuncSetAttribute(kL3, cudaFuncAttributeMaxDynamicSharedMemorySize, smE2);
    cudaFuncSetAttribute(kM2, cudaFuncAttributeMaxDynamicSharedMemorySize, smM2);
    cudaFuncSetAttribute(kO,  cudaFuncAttributeMaxDynamicSharedMemorySize, smO);

    const float invE = 1.f / (float)EE;
    const float invN = 1.f / (float)NN;
    const int EB = EE / 128;             // 6250
    const int NB = (NN + 127) / 128;     // 782

    zero_k<<<2048, 256>>>(AGG, dgo, dgi, ST);
    deg_k<<<512, 256>>>(ei, dgo, dgi);

    // merged stats: ea stats + degree-weighted x stats + x copy/stats
    stats3_k<<<1024, 256>>>(ea, x, dgo, CB, ST);

    // fold BN1 -> blobs Bp (x-half) + Be1 (ea-half), bias c1f
    foldprep_k<<<1, 128>>>(64, 64, 32, m1_g1, m1_b1, m1_w1, m1_c1, S0S, S0Q, invE,
                           (__nv_bfloat16*)Bp, (__nv_bfloat16*)Be1, c1f);

    // P = x @ W1f[0:32]
    kP<<<NB, 128, smP>>>(x, 32, NN, nullptr, nullptr, Bp, nullptr,
                         P, 64, 0, nullptr, nullptr, nullptr, nullptr, nullptr,
                         nullptr, nullptr);
    // H = lrelu(P[row] + ea @ W1f[32:64] + c1f) -> split bf16 (Hh,Hl); BN2 stats
    kE1<<<EB, 128, smP>>>(ea, 32, EE, nullptr, nullptr, Be1, c1f,
                          nullptr, 0, 0, Hh, Hl, P, ei, nullptr, S2S, S2Q);

    foldprep_k<<<1, 128>>>(64, 64, 64, m1_g2, m1_b2, m1_w2, m1_c2, S2S, S2Q, invE,
                           (__nv_bfloat16*)Be2, nullptr, c2f);

    // h2 = lrelu(H @ W2f + c2f); BN3 stats; v4-red scatter into AGG[col]
    kE2<<<EB, 128, smE2>>>(nullptr, 0, EE, Hh, Hl, Be2, c2f,
                           AGG, 0, 0, nullptr, nullptr, nullptr, ei + EE, nullptr,
                           S3S, S3Q);

    foldprep_k<<<1, 128>>>(64, 64, 64, m1_g3, m1_b3, m1_w3, m1_c3, S3S, S3Q, invE,
                           (__nv_bfloat16*)Bl3, nullptr, c3f);

    // CB[:,32:96] = AGG @ W3f + deg_in * c3f
    kL3<<<NB, 128, smE2>>>(AGG, 64, NN, nullptr, nullptr, Bl3, c3f,
                           CB, 96, 32, nullptr, nullptr, nullptr, nullptr, dgi,
                           B1S + 32, B1Q + 32);

    foldprep_k<<<1, 128>>>(96, 96, 96, m2_g1, m2_b1, m2_w1, m2_c1, B1S, B1Q, invN,
                           (__nv_bfloat16*)Bm1, nullptr, d1f);

    kM2<<<NB, 128, smM2>>>(CB, 96, NN, nullptr, nullptr, Bm1, d1f,
                           T1, 96, 0, nullptr, nullptr, nullptr, nullptr, nullptr,
                           B2S, B2Q);

    foldprep_k<<<1, 128>>>(96, 96, 96, m2_g2, m2_b2, m2_w2, m2_c2, B2S, B2Q, invN,
                           (__nv_bfloat16*)Bm2, nullptr, d2f);

    kM2<<<NB, 128, smM2>>>(T1, 96, NN, nullptr, nullptr, Bm2, d2f,
                           T2, 96, 0, nullptr, nullptr, nullptr, nullptr, nullptr,
                           B3S, B3Q);

    foldprep_k<<<1, 128>>>(96, 32, 96, m2_g3, m2_b3, m2_w3, m2_c3, B3S, B3Q, invN,
                           (__nv_bfloat16*)Bo, nullptr, d3f);

    kO<<<NB, 128, smO>>>(T2, 96, NN, nullptr, nullptr, Bo, d3f,
                         (float*)d_out, 32, 0, nullptr, nullptr, nullptr, nullptr, nullptr,
                         nullptr, nullptr);
}

// round 9
// speedup vs baseline: 1.2504x; 1.1322x over previous
#include <cuda_runtime.h>
#include <cuda_bf16.h>
#include <cstdint>
#include <cstddef>

#define NN 100000
#define EE 800000

// ---------------- scratch (static __device__ globals; no allocation) ----------------
__device__ float d_P[NN * 64];
__device__ __nv_bfloat16 d_Hh[(size_t)EE * 64];
__device__ __nv_bfloat16 d_Hl[(size_t)EE * 64];
__device__ float d_AGG[NN * 64];
__device__ float d_CB[NN * 96];
__device__ float d_T1[NN * 96];
__device__ float d_T2[NN * 96];
__device__ int   d_dgo[NN];
__device__ int   d_dgi[NN];
__device__ float d_stats[1152];
__device__ float d_c1f[64], d_c2f[64], d_c3f[64];
__device__ float d_d1f[96], d_d2f[96], d_d3f[32];
// pre-split transposed weight blobs: [Wh: NC*(K+8) bf16][Wl: NC*(K+8) bf16]
__device__ uint4 d_Bp[640];     // W1 rows 0..31  -> K=32, NC=64, KP=40
__device__ uint4 d_Be1[640];    // W1 rows 32..63 -> K=32, NC=64, KP=40
__device__ uint4 d_Be2[1152];   // W2  K=64, NC=64, KP=72
__device__ uint4 d_Bl3[1152];   // W3  K=64, NC=64, KP=72
__device__ uint4 d_Bm1[2496];   // V1  K=96, NC=96, KP=104
__device__ uint4 d_Bm2[2496];   // V2  K=96, NC=96, KP=104
__device__ uint4 d_Bo[832];     // V3  K=96, NC=32, KP=104

__device__ __forceinline__ float lrelu(float v) { return v > 0.f ? v : 0.1f * v; }

__device__ __forceinline__ uint32_t pack_hi(float a0, float a1, uint32_t& lo) {
    __nv_bfloat16 h0 = __float2bfloat16(a0), h1 = __float2bfloat16(a1);
    __nv_bfloat16 l0 = __float2bfloat16(a0 - __bfloat162float(h0));
    __nv_bfloat16 l1 = __float2bfloat16(a1 - __bfloat162float(h1));
    lo = (uint32_t)__bfloat16_as_ushort(l0) | ((uint32_t)__bfloat16_as_ushort(l1) << 16);
    return (uint32_t)__bfloat16_as_ushort(h0) | ((uint32_t)__bfloat16_as_ushort(h1) << 16);
}

// ---------------- zero scratch ----------------
__global__ void zero_k(float* agg, int* dgo, int* dgi, float* st) {
    int i = blockIdx.x * blockDim.x + threadIdx.x;
    int stride = gridDim.x * blockDim.x;
    for (int j = i; j < NN * 64; j += stride) agg[j] = 0.f;
    for (int j = i; j < NN; j += stride) { dgo[j] = 0; dgi[j] = 0; }
    for (int j = i; j < 1152; j += stride) st[j] = 0.f;
}

// ---------------- degree counts ----------------
__global__ void deg_k(const int* __restrict__ ei, int* dgo, int* dgi) {
    int i = blockIdx.x * blockDim.x + threadIdx.x;
    int stride = gridDim.x * blockDim.x;
    for (int e = i; e < EE; e += stride) {
        atomicAdd(&dgo[ei[e]], 1);
        atomicAdd(&dgi[ei[EE + e]], 1);
    }
}

// ---------------- merged 32-wide column stats (3 segments) ----------------
// blocks [0,512):   plain stats of ea (EE x 32)        -> S0S+32 / S0Q+32
// blocks [512,768): degree-weighted stats of x         -> S0S / S0Q
// blocks [768,1024): stats of x + copy into CB[:,0:32] -> B1S / B1Q
__global__ void stats3_k(const float* __restrict__ ea, const float* __restrict__ x,
                         const int* __restrict__ dgo, float* __restrict__ cb,
                         float* __restrict__ ST) {
    int b = blockIdx.x, tid = threadIdx.x, c = tid & 31;
    const float* A; int nrows, lb, G, mode;
    float *sum, *sq;
    if (b < 512)      { mode = 0; A = ea; nrows = EE; lb = b;       G = 512; sum = ST + 32;  sq = ST + 128; }
    else if (b < 768) { mode = 1; A = x;  nrows = NN; lb = b - 512; G = 256; sum = ST;       sq = ST + 96; }
    else              { mode = 2; A = x;  nrows = NN; lb = b - 768; G = 256; sum = ST + 576; sq = ST + 672; }
    int i = lb * 256 + tid, stride = G * 256, tot = nrows * 32;
    float s = 0.f, q = 0.f;
    for (int j = i; j < tot; j += stride) {
        float v = A[j];
        if (mode == 1) {
            float wf = (float)dgo[j >> 5];
            s += wf * v; q += wf * v * v;
        } else {
            s += v; q += v * v;
            if (mode == 2) cb[(j >> 5) * 96 + (j & 31)] = v;
        }
    }
    __shared__ float red[256];
    red[tid] = s;
    __syncthreads();
    if (tid < 32) {
        float a = 0.f;
#pragma unroll
        for (int g = 0; g < 8; g++) a += red[tid + 32 * g];
        atomicAdd(&sum[c], a);
    }
    __syncthreads();
    red[tid] = q;
    __syncthreads();
    if (tid < 32) {
        float a = 0.f;
#pragma unroll
        for (int g = 0; g < 8; g++) a += red[tid + 32 * g];
        atomicAdd(&sq[c], a);
    }
}

// ---------------- fold BN into next Linear + emit split/transposed blob ----------------
// Grid-parallel: every block recomputes the tiny s,t vectors; cf and blob are
// grid-strided so the work spreads over 24 SMs instead of one.
__global__ void foldprep_k(int K, int NC, int ksplit,
                           const float* __restrict__ g, const float* __restrict__ b,
                           const float* __restrict__ W, const float* __restrict__ c,
                           const float* __restrict__ ssum, const float* __restrict__ ssq,
                           float inv_cnt,
                           __nv_bfloat16* __restrict__ blobA,
                           __nv_bfloat16* __restrict__ blobB,
                           float* __restrict__ cf) {
    __shared__ float s[96], t[96];
    int tid = threadIdx.x;
    int gt = blockIdx.x * blockDim.x + tid;
    int GS = gridDim.x * blockDim.x;
    if (tid < K) {
        float m = ssum[tid] * inv_cnt;
        float v = ssq[tid] * inv_cnt - m * m;
        float sc = g[tid] * rsqrtf(v + 1e-5f);
        s[tid] = sc;
        t[tid] = b[tid] - m * sc;
    }
    __syncthreads();
    int KPa = ksplit + 8, KPb = (K - ksplit) + 8;
    for (int j = gt; j < NC; j += GS) {
        float acc = c[j];
        for (int k = 0; k < K; k++) acc += t[k] * W[k * NC + j];
        cf[j] = acc;
    }
    for (int i = gt; i < K * NC; i += GS) {
        int k = i / NC, n = i - k * NC;
        float w = s[k] * W[i];
        __nv_bfloat16 h = __float2bfloat16(w);
        __nv_bfloat16 l = __float2bfloat16(w - __bfloat162float(h));
        if (k < ksplit) {
            blobA[n * KPa + k] = h;
            blobA[NC * KPa + n * KPa + k] = l;
        } else {
            int kk = k - ksplit;
            blobB[n * KPb + kk] = h;
            blobB[NC * KPb + n * KPb + kk] = l;
        }
    }
}

// ---------------- mma.sync fused GEMM: out[M,NC] = epi(A[M,K] @ W[K,NC]) ----------------
// bf16 3-term split: D = Ah*Wh + Ah*Wl + Al*Wh. 128 rows/block, 4 warps.
// (R3 structure verbatim: per-thread gather, scalar coalesced atomic scatter.)
template <int K, int NC, bool RELU, bool STATS, bool GATHERP, bool SCATTER,
          bool DEGBIAS, bool ASPLIT, bool OUTSPLIT>
__global__ void __launch_bounds__(128)
tgemm_k(const float* __restrict__ A, int lda, int M,
        const __nv_bfloat16* __restrict__ Ahg, const __nv_bfloat16* __restrict__ Alg,
        const uint4* __restrict__ Bblob,
        const float* __restrict__ bias,
        float* __restrict__ out, int ldo, int ocol,
        __nv_bfloat16* __restrict__ Oh, __nv_bfloat16* __restrict__ Ol,
        const float* __restrict__ Pg, const int* __restrict__ gidx,
        const int* __restrict__ degb,
        float* __restrict__ ssum, float* __restrict__ ssq) {
    constexpr int KP = K + 8;                    // padded row -> conflict-free frags
    constexpr int SW = NC + 2;                   // staging row stride (floats)
    constexpr int MAXW = (KP > SW) ? KP : SW;
    constexpr int S1 = 128 * MAXW * 4;           // bytes: A(hi+lo) region, reused as staging
    constexpr int NT = NC / 8;
    constexpr int KS = K / 16;

    extern __shared__ unsigned char sm[];
    __nv_bfloat16* smAh = (__nv_bfloat16*)sm;
    __nv_bfloat16* smAl = smAh + 128 * KP;
    __nv_bfloat16* smWh = (__nv_bfloat16*)(sm + S1);
    __nv_bfloat16* smWl = smWh + NC * KP;
    float* stg = (float*)sm;

    const int tid = threadIdx.x;
    const int lane = tid & 31, wrp = tid >> 5;
    const int g8 = lane >> 2, tg = lane & 3;
    const int row0 = blockIdx.x * 128;

    // ---- W copy (blob layout == smem layout) ----
    {
        uint4* wd = (uint4*)smWh;
        for (int i = tid; i < NC * KP / 4; i += 128) wd[i] = Bblob[i];
    }
    // ---- A fill (+ fp32->bf16 hi/lo split unless pre-split) ----
    {
        constexpr int KH = K / 2;
        for (int idx = tid; idx < 128 * KH; idx += 128) {
            int row = idx / KH;
            int k = (idx - row * KH) * 2;
            int g = row0 + row;
            uint32_t hw = 0, lw = 0;
            if (ASPLIT) {
                if (g < M) {
                    hw = *(const uint32_t*)(Ahg + (size_t)g * K + k);
                    lw = *(const uint32_t*)(Alg + (size_t)g * K + k);
                }
            } else {
                float ax = 0.f, ay = 0.f;
                if (g < M) {
                    float2 t = *(const float2*)(A + (size_t)g * lda + k);
                    ax = t.x; ay = t.y;
                }
                hw = pack_hi(ax, ay, lw);
            }
            *(uint32_t*)(smAh + row * KP + k) = hw;
            *(uint32_t*)(smAl + row * KP + k) = lw;
        }
    }
    __syncthreads();

    // ---- mma compute ----
    float acc[2][NT][4];
#pragma unroll
    for (int mt = 0; mt < 2; mt++)
#pragma unroll
        for (int nt = 0; nt < NT; nt++)
#pragma unroll
            for (int j = 0; j < 4; j++) acc[mt][nt][j] = 0.f;

    const __nv_bfloat16* APTR[3] = {smAh, smAh, smAl};
    const __nv_bfloat16* WPTR[3] = {smWh, smWl, smWh};
#pragma unroll
    for (int t = 0; t < 3; t++) {
        const __nv_bfloat16* Ab = APTR[t];
        const __nv_bfloat16* Wb = WPTR[t];
#pragma unroll
        for (int ks = 0; ks < KS; ks++) {
            uint32_t a[2][4];
#pragma unroll
            for (int mt = 0; mt < 2; mt++) {
                int row = wrp * 32 + mt * 16 + g8;
                const uint32_t* p  = (const uint32_t*)(Ab + row * KP + ks * 16 + tg * 2);
                const uint32_t* p8 = (const uint32_t*)(Ab + (row + 8) * KP + ks * 16 + tg * 2);
                a[mt][0] = p[0];  a[mt][1] = p8[0];
                a[mt][2] = p[4];  a[mt][3] = p8[4];
            }
#pragma unroll
            for (int nt = 0; nt < NT; nt++) {
                const uint32_t* q = (const uint32_t*)(Wb + (nt * 8 + g8) * KP + ks * 16 + tg * 2);
                uint32_t b0 = q[0], b1 = q[4];
#pragma unroll
                for (int mt = 0; mt < 2; mt++) {
                    asm volatile(
                        "mma.sync.aligned.m16n8k16.row.col.f32.bf16.bf16.f32 "
                        "{%0,%1,%2,%3}, {%4,%5,%6,%7}, {%8,%9}, {%0,%1,%2,%3};"
                        : "+f"(acc[mt][nt][0]), "+f"(acc[mt][nt][1]),
                          "+f"(acc[mt][nt][2]), "+f"(acc[mt][nt][3])
                        : "r"(a[mt][0]), "r"(a[mt][1]), "r"(a[mt][2]), "r"(a[mt][3]),
                          "r"(b0), "r"(b1));
                }
            }
        }
    }
    __syncthreads();   // A reads done; staging may overwrite

    // ---- fragments -> staging ----
#pragma unroll
    for (int mt = 0; mt < 2; mt++) {
        int r0 = wrp * 32 + mt * 16 + g8;
#pragma unroll
        for (int nt = 0; nt < NT; nt++) {
            int c = nt * 8 + tg * 2;
            *(float2*)&stg[r0 * SW + c]       = make_float2(acc[mt][nt][0], acc[mt][nt][1]);
            *(float2*)&stg[(r0 + 8) * SW + c] = make_float2(acc[mt][nt][2], acc[mt][nt][3]);
        }
    }
    __syncthreads();

    // ---- per-row epilogue: thread tid owns row row0+tid ----
    const int g = row0 + tid;
    const bool valid = g < M;
    int other = 0;
    if ((SCATTER || GATHERP) && valid) other = gidx[g];
    float db = 1.f;
    if (DEGBIAS) db = valid ? (float)degb[g] : 0.f;

#pragma unroll
    for (int ch = 0; ch < NC; ch += 32) {
        float v[32];
#pragma unroll
        for (int c = 0; c < 32; c += 2) {
            float2 t = *(float2*)&stg[tid * SW + ch + c];
            v[c] = t.x; v[c + 1] = t.y;
        }
        if (GATHERP) {
#pragma unroll
            for (int j = 0; j < 32; j += 4) {
                float4 t = valid ? *(const float4*)(Pg + (size_t)other * 64 + ch + j)
                                 : make_float4(0.f, 0.f, 0.f, 0.f);
                v[j] += t.x; v[j + 1] += t.y; v[j + 2] += t.z; v[j + 3] += t.w;
            }
        }
#pragma unroll
        for (int j = 0; j < 32; j++) {
            float b = bias ? __ldg(bias + ch + j) : 0.f;
            float t = v[j] + db * b;
            if (RELU) t = lrelu(t);
            v[j] = t;
        }
        if (!SCATTER && !OUTSPLIT) {
            if (valid) {
#pragma unroll
                for (int j = 0; j < 32; j += 4)
                    *(float4*)(out + (size_t)g * ldo + ocol + ch + j) =
                        make_float4(v[j], v[j + 1], v[j + 2], v[j + 3]);
            }
        }
        if (STATS || SCATTER || OUTSPLIT) {
#pragma unroll
            for (int c = 0; c < 32; c += 2)
                *(float2*)&stg[tid * SW + ch + c] =
                    make_float2(valid ? v[c] : 0.f, valid ? v[c + 1] : 0.f);
        }
    }

    if (STATS || SCATTER || OUTSPLIT) __syncthreads();

    if (SCATTER) {
        // warp-per-row coalesced scalar atomics (NC == 64) — R3 fast path
        for (int r = wrp; r < 128; r += 4) {
            int gr = row0 + r;
            if (gr < M) {
                int dst = gidx[gr];
                float* ap = out + (size_t)dst * 64;
                atomicAdd(ap + lane,      stg[r * SW + lane]);
                atomicAdd(ap + 32 + lane, stg[r * SW + 32 + lane]);
            }
        }
    }

    if (OUTSPLIT) {
        // coalesced packed split write (NC == 64)
        for (int i = tid; i < 128 * 32; i += 128) {
            int r = i >> 5, c2 = i & 31;
            int gr = row0 + r;
            if (gr < M) {
                uint32_t lw, hw = pack_hi(stg[r * SW + 2 * c2], stg[r * SW + 2 * c2 + 1], lw);
                ((uint32_t*)Oh)[(size_t)gr * 32 + c2] = hw;
                ((uint32_t*)Ol)[(size_t)gr * 32 + c2] = lw;
            }
        }
    }

    if (STATS) {
        if (tid < NC) {
            float s = 0.f, q = 0.f;
            for (int r = 0; r < 128; r++) {
                float t = stg[r * SW + tid];
                s += t; q += t * t;
            }
            atomicAdd(&ssum[tid], s);
            atomicAdd(&ssq[tid], q);
        }
    }
}

// ---------------- host ----------------
#define SYM(ptr, arr) do { void* _p = nullptr; cudaGetSymbolAddress(&_p, arr); ptr = (decltype(ptr))_p; } while (0)

static constexpr int smem_sz(int K, int NC) {
    int KP = K + 8, SW = NC + 2;
    int MAXW = KP > SW ? KP : SW;
    return 128 * MAXW * 4 + NC * KP * 4;
}

extern "C" void kernel_launch(void* const* d_in, const int* in_sizes, int n_in,
                              void* d_out, int out_size) {
    const float* x  = (const float*)d_in[0];
    const int*   ei = (const int*)d_in[1];
    const float* ea = (const float*)d_in[2];
    const float* m1_g1 = (const float*)d_in[5],  *m1_b1 = (const float*)d_in[6];
    const float* m1_w1 = (const float*)d_in[7],  *m1_c1 = (const float*)d_in[8];
    const float* m1_g2 = (const float*)d_in[9],  *m1_b2 = (const float*)d_in[10];
    const float* m1_w2 = (const float*)d_in[11], *m1_c2 = (const float*)d_in[12];
    const float* m1_g3 = (const float*)d_in[13], *m1_b3 = (const float*)d_in[14];
    const float* m1_w3 = (const float*)d_in[15], *m1_c3 = (const float*)d_in[16];
    const float* m2_g1 = (const float*)d_in[17], *m2_b1 = (const float*)d_in[18];
    const float* m2_w1 = (const float*)d_in[19], *m2_c1 = (const float*)d_in[20];
    const float* m2_g2 = (const float*)d_in[21], *m2_b2 = (const float*)d_in[22];
    const float* m2_w2 = (const float*)d_in[23], *m2_c2 = (const float*)d_in[24];
    const float* m2_g3 = (const float*)d_in[25], *m2_b3 = (const float*)d_in[26];
    const float* m2_w3 = (const float*)d_in[27], *m2_c3 = (const float*)d_in[28];

    float *P, *AGG, *CB, *T1, *T2, *ST;
    __nv_bfloat16 *Hh, *Hl;
    int *dgo, *dgi;
    float *c1f, *c2f, *c3f, *d1f, *d2f, *d3f;
    uint4 *Bp, *Be1, *Be2, *Bl3, *Bm1, *Bm2, *Bo;
    SYM(P, d_P); SYM(Hh, d_Hh); SYM(Hl, d_Hl); SYM(AGG, d_AGG); SYM(CB, d_CB);
    SYM(T1, d_T1); SYM(T2, d_T2); SYM(ST, d_stats);
    SYM(dgo, d_dgo); SYM(dgi, d_dgi);
    SYM(c1f, d_c1f); SYM(c2f, d_c2f); SYM(c3f, d_c3f);
    SYM(d1f, d_d1f); SYM(d2f, d_d2f); SYM(d3f, d_d3f);
    SYM(Bp, d_Bp); SYM(Be1, d_Be1); SYM(Be2, d_Be2); SYM(Bl3, d_Bl3);
    SYM(Bm1, d_Bm1); SYM(Bm2, d_Bm2); SYM(Bo, d_Bo);

    float *S0S = ST + 0,   *S0Q = ST + 96;
    float *S2S = ST + 192, *S2Q = ST + 288;
    float *S3S = ST + 384, *S3Q = ST + 480;
    float *B1S = ST + 576, *B1Q = ST + 672;
    float *B2S = ST + 768, *B2Q = ST + 864;
    float *B3S = ST + 960, *B3Q = ST + 1056;

    // <K,NC,RELU,STATS,GATHERP,SCATTER,DEGBIAS,ASPLIT,OUTSPLIT>
    auto kP  = tgemm_k<32, 64, false, false, false, false, false, false, false>;
    auto kE1 = tgemm_k<32, 64, true,  true,  true,  false, false, false, true >;
    auto kE2 = tgemm_k<64, 64, true,  true,  false, true,  false, true,  false>;
    auto kL3 = tgemm_k<64, 64, false, true,  false, false, true,  false, false>;
    auto kM2 = tgemm_k<96, 96, true,  true,  false, false, false, false, false>;
    auto kO  = tgemm_k<96, 32, false, false, false, false, false, false, false>;

    constexpr int smP  = smem_sz(32, 64);   // 44032
    constexpr int smE2 = smem_sz(64, 64);   // 55296
    constexpr int smM2 = smem_sz(96, 96);   // 93184
    constexpr int smO  = smem_sz(96, 32);   // 66560

    cudaFuncSetAttribute(kP,  cudaFuncAttributeMaxDynamicSharedMemorySize, smP);
    cudaFuncSetAttribute(kE1, cudaFuncAttributeMaxDynamicSharedMemorySize, smP);
    cudaFuncSetAttribute(kE2, cudaFuncAttributeMaxDynamicSharedMemorySize, smE2);
    cudaFuncSetAttribute(kL3, cudaFuncAttributeMaxDynamicSharedMemorySize, smE2);
    cudaFuncSetAttribute(kM2, cudaFuncAttributeMaxDynamicSharedMemorySize, smM2);
    cudaFuncSetAttribute(kO,  cudaFuncAttributeMaxDynamicSharedMemorySize, smO);

    const float invE = 1.f / (float)EE;
    const float invN = 1.f / (float)NN;
    const int EB = EE / 128;             // 6250
    const int NB = (NN + 127) / 128;     // 782

    zero_k<<<2048, 256>>>(AGG, dgo, dgi, ST);
    deg_k<<<512, 256>>>(ei, dgo, dgi);

    // merged stats: ea stats + degree-weighted x stats + x copy/stats
    stats3_k<<<1024, 256>>>(ea, x, dgo, CB, ST);

    // fold BN1 -> blobs Bp (x-half) + Be1 (ea-half), bias c1f
    foldprep_k<<<24, 128>>>(64, 64, 32, m1_g1, m1_b1, m1_w1, m1_c1, S0S, S0Q, invE,
                            (__nv_bfloat16*)Bp, (__nv_bfloat16*)Be1, c1f);

    // P = x @ W1f[0:32]
    kP<<<NB, 128, smP>>>(x, 32, NN, nullptr, nullptr, Bp, nullptr,
                         P, 64, 0, nullptr, nullptr, nullptr, nullptr, nullptr,
                         nullptr, nullptr);
    // H = lrelu(P[row] + ea @ W1f[32:64] + c1f) -> split bf16 (Hh,Hl); BN2 stats
    kE1<<<EB, 128, smP>>>(ea, 32, EE, nullptr, nullptr, Be1, c1f,
                          nullptr, 0, 0, Hh, Hl, P, ei, nullptr, S2S, S2Q);

    foldprep_k<<<24, 128>>>(64, 64, 64, m1_g2, m1_b2, m1_w2, m1_c2, S2S, S2Q, invE,
                            (__nv_bfloat16*)Be2, nullptr, c2f);

    // h2 = lrelu(H @ W2f + c2f); BN3 stats; coalesced scalar-atomic scatter into AGG
    kE2<<<EB, 128, smE2>>>(nullptr, 0, EE, Hh, Hl, Be2, c2f,
                           AGG, 0, 0, nullptr, nullptr, nullptr, ei + EE, nullptr,
                           S3S, S3Q);

    foldprep_k<<<24, 128>>>(64, 64, 64, m1_g3, m1_b3, m1_w3, m1_c3, S3S, S3Q, invE,
                            (__nv_bfloat16*)Bl3, nullptr, c3f);

    // CB[:,32:96] = AGG @ W3f + deg_in * c3f
    kL3<<<NB, 128, smE2>>>(AGG, 64, NN, nullptr, nullptr, Bl3, c3f,
                           CB, 96, 32, nullptr, nullptr, nullptr, nullptr, dgi,
                           B1S + 32, B1Q + 32);

    foldprep_k<<<24, 128>>>(96, 96, 96, m2_g1, m2_b1, m2_w1, m2_c1, B1S, B1Q, invN,
                            (__nv_bfloat16*)Bm1, nullptr, d1f);

    kM2<<<NB, 128, smM2>>>(CB, 96, NN, nullptr, nullptr, Bm1, d1f,
                           T1, 96, 0, nullptr, nullptr, nullptr, nullptr, nullptr,
                           B2S, B2Q);

    foldprep_k<<<24, 128>>>(96, 96, 96, m2_g2, m2_b2, m2_w2, m2_c2, B2S, B2Q, invN,
                            (__nv_bfloat16*)Bm2, nullptr, d2f);

    kM2<<<NB, 128, smM2>>>(T1, 96, NN, nullptr, nullptr, Bm2, d2f,
                           T2, 96, 0, nullptr, nullptr, nullptr, nullptr, nullptr,
                           B3S, B3Q);

    foldprep_k<<<24, 128>>>(96, 32, 96, m2_g3, m2_b3, m2_w3, m2_c3, B3S, B3Q, invN,
                            (__nv_bfloat16*)Bo, nullptr, d3f);

    kO<<<NB, 128, smO>>>(T2, 96, NN, nullptr, nullptr, Bo, d3f,
                         (float*)d_out, 32, 0, nullptr, nullptr, nullptr, nullptr, nullptr,
                         nullptr, nullptr);
}